// round 5
// baseline (speedup 1.0000x reference)
#include <cuda_runtime.h>
#include <cuda_fp16.h>
#include <cstdint>

#define Bb 512
#define Tt 256
#define Hh 1024
#define NCTA 128
#define KCH 64
#define NCHUNK 16          // 1024 / 64
#define NSTG 6
#define STAGE_BYTES 32768  // A tile 16KB + B tile 16KB
#define NTHREADS 512
#define GP 132             // gates smem pitch (floats)
#define SMEM_DYN (1024 + 2048 + NSTG*STAGE_BYTES)

// persistent device state (static allocation — no cudaMalloc)
__device__ __half g_h[Bb * Hh];            // hidden state, fp16 [512,1024]
__device__ __half g_wp[32 * 128 * Hh];     // packed W_hh slabs, fp16
__device__ float  g_xT[Tt * Bb];           // x transposed [T,B]
__device__ int    g_flag[4 * 32];          // [mb][jb] = #steps whose h is published

// ---------------- helpers ----------------
__device__ __forceinline__ uint32_t smem_u32(const void* p) {
    uint32_t a;
    asm("{ .reg .u64 t; cvta.to.shared.u64 t, %1; cvt.u32.u64 %0, t; }" : "=r"(a) : "l"(p));
    return a;
}
__device__ __forceinline__ void cp16(uint32_t dst, const void* src) {
    unsigned long long g = __cvta_generic_to_global(src);
    asm volatile("cp.async.cg.shared.global [%0], [%1], 16;" :: "r"(dst), "l"(g) : "memory");
}
__device__ __forceinline__ void cp_commit() {
    asm volatile("cp.async.commit_group;" ::: "memory");
}
__device__ __forceinline__ void cp_wait4() {
    asm volatile("cp.async.wait_group 4;" ::: "memory");
}
__device__ __forceinline__ void cp_wait0() {
    asm volatile("cp.async.wait_group 0;" ::: "memory");
}
__device__ __forceinline__ void ldsm_x4(uint32_t (&r)[4], uint32_t addr) {
    asm volatile("ldmatrix.sync.aligned.m8n8.x4.shared.b16 {%0,%1,%2,%3}, [%4];"
        : "=r"(r[0]), "=r"(r[1]), "=r"(r[2]), "=r"(r[3]) : "r"(addr));
}
__device__ __forceinline__ void mma16816(float (&d)[4], const uint32_t (&a)[4],
                                         uint32_t b0, uint32_t b1) {
    asm volatile("mma.sync.aligned.m16n8k16.row.col.f32.f16.f16.f32 "
        "{%0,%1,%2,%3}, {%4,%5,%6,%7}, {%8,%9}, {%0,%1,%2,%3};"
        : "+f"(d[0]), "+f"(d[1]), "+f"(d[2]), "+f"(d[3])
        : "r"(a[0]), "r"(a[1]), "r"(a[2]), "r"(a[3]), "r"(b0), "r"(b1));
}
__device__ __forceinline__ float sigm(float x) { return 1.0f / (1.0f + __expf(-x)); }
__device__ __forceinline__ float tanh_(float x) { return 2.0f / (1.0f + __expf(-2.0f * x)) - 1.0f; }

// acquire-load a pair of adjacent flags (producers 2p, 2p+1)
__device__ __forceinline__ uint64_t ld_flags(const int* p) {
    uint32_t lo, hi;
    asm volatile("ld.acquire.gpu.global.v2.u32 {%0,%1}, [%2];"
        : "=r"(lo), "=r"(hi) : "l"(p) : "memory");
    return ((uint64_t)hi << 32) | lo;
}
__device__ __forceinline__ bool flags_ok(uint64_t v, int t) {
    return ((int)(v & 0xffffffffu) >= t) && ((int)(v >> 32) >= t);
}
__device__ __forceinline__ void st_flag_release(int* p, int v) {
    asm volatile("st.release.gpu.global.b32 [%0], %1;" :: "l"(p), "r"(v) : "memory");
}

// ---------------- prepack: weights->fp16 slabs, x transpose, h=0, out=b_out ----------------
__global__ void prepack_kernel(const float* __restrict__ x,
                               const float* __restrict__ W_hh,
                               const float* __restrict__ b_out,
                               float* __restrict__ out)
{
    long i = (long)blockIdx.x * blockDim.x + threadIdx.x;
    long stride = (long)gridDim.x * blockDim.x;
    // packed weights: slab jb, row r = gate*32 + jj  ->  W_hh[gate*H + jb*32 + jj, k]
    for (long idx = i; idx < (long)32 * 128 * Hh; idx += stride) {
        int k  = (int)(idx & (Hh - 1));
        int r  = (int)((idx >> 10) & 127);
        int jb = (int)(idx >> 17);
        int g  = r >> 5, jj = r & 31;
        g_wp[idx] = __float2half(W_hh[(long)(g * Hh + jb * 32 + jj) * Hh + k]);
    }
    for (long idx = i; idx < (long)Tt * Bb; idx += stride) {
        int b = (int)(idx & (Bb - 1));
        int t = (int)(idx >> 9);
        g_xT[idx] = x[(long)b * Tt + t];
    }
    for (long idx = i; idx < (long)Bb * Hh; idx += stride)
        g_h[idx] = __float2half(0.0f);
    float bo = b_out[0];
    for (long idx = i; idx < (long)Bb * Tt; idx += stride)
        out[idx] = bo;
    if (i < 128) g_flag[i] = 0;
}

// ---------------- persistent LSTM kernel ----------------
__global__ void __launch_bounds__(NTHREADS, 1) lstm_main(
    const float* __restrict__ W_ih, const float* __restrict__ b_ih,
    const float* __restrict__ b_hh, const float* __restrict__ W_out,
    float* __restrict__ out)
{
    extern __shared__ char smem_raw[];
    uint32_t sraw = smem_u32(smem_raw);
    uint32_t s0 = (sraw + 1023u) & ~1023u;
    char* sm0 = smem_raw + (s0 - sraw);

    const int tid = threadIdx.x;
    const int l   = tid & 31;
    const int w   = tid >> 5;
    const int cta = blockIdx.x;
    const int mb = cta >> 5, jb = cta & 31;
    const int row0 = mb * 128, j0 = jb * 32;
    const int start = jb >> 1;                 // K-chunk rotation: own columns first
    const int* fbase = g_flag + mb * 32;
    int* myflag = g_flag + mb * 32 + jb;

    float* bias_s = (float*)(sm0);           // [128]
    float* wih_s  = (float*)(sm0 + 512);     // [128]
    float* wout_s = (float*)(sm0 + 1024);    // [32]
    const uint32_t TILE0 = s0 + 2048;        // pipeline stages / gates scratch (aliased)
    float* gsm = (float*)(sm0 + 2048);       // gates [128][GP] fp32, aliases stages

    if (tid < 128) {
        int g = tid >> 5, jj = tid & 31;
        int grow = g * Hh + j0 + jj;
        bias_s[tid] = b_ih[grow] + b_hh[grow];
        wih_s[tid]  = W_ih[grow];
    }
    if (tid < 32) wout_s[tid] = W_out[j0 + tid];
    __syncthreads();

    // warp tiling: 16 warps, M0 in {0,32,64,96} (w&3), N0 in {0,32,64,96} (w>>2)
    const int M0 = (w & 3) * 32;
    const int N0 = (w >> 2) * 32;
    // ldmatrix lane address components
    const int arow0 = M0 + (l & 7) + 8 * ((l >> 3) & 1);   // +16*mi
    const int agrn0 = (l >> 4);                             // + 2*kk
    const int brow0 = N0 + (l & 7) + 8 * (l >> 4);          // +16*p
    const int bgrn0 = (l >> 3) & 1;                         // + 2*kk
    const int l4 = l >> 2, l2 = (l & 3) * 2;

    const char* baseA = (const char*)g_h  + (size_t)row0 * (Hh * 2);
    const char* baseB = (const char*)g_wp + (size_t)jb * 128 * (Hh * 2);

    float c[8];
#pragma unroll
    for (int m = 0; m < 8; m++) c[m] = 0.0f;

    const int row = tid >> 2, q4 = tid & 3;   // epilogue mapping: 4 threads per batch row

#pragma unroll 1
    for (int t = 0; t < Tt; t++) {
        // ---- B (weights) prologue: independent of h, no gating ----
        // (previous iteration ended with __syncthreads -> gsm alias safe)
#pragma unroll
        for (int s = 0; s < NSTG - 1; s++) {
            int pch = (start + s) & 15;
            uint32_t tb = TILE0 + s * STAGE_BYTES;
#pragma unroll
            for (int j = 0; j < 2; j++) {
                int q = tid + 512 * j;
                int r = q >> 3, cb = q & 7;
                uint32_t so = (uint32_t)(r * 128) + (uint32_t)((cb ^ (r & 7)) << 4);
                size_t go = (size_t)r * (Hh * 2) + (size_t)pch * (KCH * 2) + (size_t)cb * 16;
                cp16(tb + 16384 + so, baseB + go);
            }
            cp_commit();
        }

        // ---- A (h) prologue: flag-gated per chunk, flags prefetched in batch ----
        uint64_t fpre[NSTG - 1];
#pragma unroll
        for (int s = 0; s < NSTG - 1; s++) {
            int pch = (start + s) & 15;
            fpre[s] = ld_flags(fbase + 2 * pch);
        }
#pragma unroll
        for (int s = 0; s < NSTG - 1; s++) {
            int pch = (start + s) & 15;
            while (!flags_ok(fpre[s], t)) { __nanosleep(64); fpre[s] = ld_flags(fbase + 2 * pch); }
            uint32_t tb = TILE0 + s * STAGE_BYTES;
#pragma unroll
            for (int j = 0; j < 2; j++) {
                int q = tid + 512 * j;
                int r = q >> 3, cb = q & 7;
                uint32_t so = (uint32_t)(r * 128) + (uint32_t)((cb ^ (r & 7)) << 4);
                size_t go = (size_t)r * (Hh * 2) + (size_t)pch * (KCH * 2) + (size_t)cb * 16;
                cp16(tb + so, baseA + go);
            }
            cp_commit();
        }

        float acc[2][4][4];
#pragma unroll
        for (int mi = 0; mi < 2; mi++)
#pragma unroll
            for (int ni = 0; ni < 4; ni++)
#pragma unroll
                for (int e = 0; e < 4; e++) acc[mi][ni][e] = 0.0f;

        // prefetch flag pair for the first mainloop-issued chunk
        uint64_t fnext = ld_flags(fbase + 2 * ((start + NSTG - 1) & 15));

        // ---- main K loop, 16 chunks of 64, register-double-buffered fragments ----
#pragma unroll 1
        for (int ch = 0; ch < NCHUNK; ch++) {
            cp_wait4();
            __syncthreads();

            uint32_t As = TILE0 + (ch % NSTG) * STAGE_BYTES;
            uint32_t Bs = As + 16384;

            uint32_t a[2][2][4];   // [buf][mi][4]
            uint32_t bf[2][4][2];  // [buf][ni][2]
            // prefetch kk=0
#pragma unroll
            for (int mi = 0; mi < 2; mi++) {
                int r2 = arow0 + 16 * mi;
                ldsm_x4(a[0][mi], As + (uint32_t)(r2 * 128) + (uint32_t)((agrn0 ^ (r2 & 7)) << 4));
            }
#pragma unroll
            for (int p = 0; p < 2; p++) {
                uint32_t b4[4];
                int r2 = brow0 + 16 * p;
                ldsm_x4(b4, Bs + (uint32_t)(r2 * 128) + (uint32_t)((bgrn0 ^ (r2 & 7)) << 4));
                bf[0][2 * p][0] = b4[0]; bf[0][2 * p][1] = b4[1];
                bf[0][2 * p + 1][0] = b4[2]; bf[0][2 * p + 1][1] = b4[3];
            }
#pragma unroll
            for (int kk = 0; kk < 4; kk++) {
                int cur = kk & 1, nxt = cur ^ 1;
                if (kk < 3) {
                    int gr_a = 2 * (kk + 1) + agrn0;
                    int gr_b = 2 * (kk + 1) + bgrn0;
#pragma unroll
                    for (int mi = 0; mi < 2; mi++) {
                        int r2 = arow0 + 16 * mi;
                        ldsm_x4(a[nxt][mi], As + (uint32_t)(r2 * 128) + (uint32_t)((gr_a ^ (r2 & 7)) << 4));
                    }
#pragma unroll
                    for (int p = 0; p < 2; p++) {
                        uint32_t b4[4];
                        int r2 = brow0 + 16 * p;
                        ldsm_x4(b4, Bs + (uint32_t)(r2 * 128) + (uint32_t)((gr_b ^ (r2 & 7)) << 4));
                        bf[nxt][2 * p][0] = b4[0]; bf[nxt][2 * p][1] = b4[1];
                        bf[nxt][2 * p + 1][0] = b4[2]; bf[nxt][2 * p + 1][1] = b4[3];
                    }
                }
#pragma unroll
                for (int mi = 0; mi < 2; mi++)
#pragma unroll
                    for (int ni = 0; ni < 4; ni++)
                        mma16816(acc[mi][ni], a[cur][mi], bf[cur][ni][0], bf[cur][ni][1]);
            }

            // issue loads for chunk ch+NSTG-1 (flag-gated; flag prefetched last iter)
            int nc = ch + NSTG - 1;
            if (nc < NCHUNK) {
                int pch = (start + nc) & 15;
                while (!flags_ok(fnext, t)) { __nanosleep(64); fnext = ld_flags(fbase + 2 * pch); }
                uint32_t tb = TILE0 + (nc % NSTG) * STAGE_BYTES;
#pragma unroll
                for (int j = 0; j < 2; j++) {
                    int q = tid + 512 * j;
                    int r = q >> 3, cb = q & 7;
                    uint32_t so = (uint32_t)(r * 128) + (uint32_t)((cb ^ (r & 7)) << 4);
                    size_t go = (size_t)r * (Hh * 2) + (size_t)pch * (KCH * 2) + (size_t)cb * 16;
                    cp16(tb + so,         baseA + go);
                    cp16(tb + 16384 + so, baseB + go);
                }
                if (nc + 1 < NCHUNK)
                    fnext = ld_flags(fbase + 2 * ((start + nc + 1) & 15));  // prefetch, hidden by next MMA
            }
            cp_commit();
        }
        cp_wait0();
        __syncthreads();   // all warps done reading stages before gates alias write

        // ---- store gates to smem (pitch GP=132, float2) ----
#pragma unroll
        for (int mi = 0; mi < 2; mi++)
#pragma unroll
            for (int ni = 0; ni < 4; ni++) {
                int r2 = M0 + mi * 16 + l4;
                int col = N0 + ni * 8 + l2;
                *(float2*)&gsm[r2 * GP + col]       = make_float2(acc[mi][ni][0], acc[mi][ni][1]);
                *(float2*)&gsm[(r2 + 8) * GP + col] = make_float2(acc[mi][ni][2], acc[mi][ni][3]);
            }
        __syncthreads();

        // ---- combine: 512 threads, thread = 4*row + q4, 8 jj each ----
        {
            float xv = g_xT[t * Bb + row0 + row];
            int cb0 = row * GP + q4 * 8;
            float Gi[8], Gg[8], ig[8];
#pragma unroll
            for (int qq = 0; qq < 2; qq++) {
                float4 vi = *(const float4*)&gsm[cb0 + 0  + 4 * qq];
                float4 vg = *(const float4*)&gsm[cb0 + 64 + 4 * qq];
                Gi[4 * qq] = vi.x; Gi[4 * qq + 1] = vi.y; Gi[4 * qq + 2] = vi.z; Gi[4 * qq + 3] = vi.w;
                Gg[4 * qq] = vg.x; Gg[4 * qq + 1] = vg.y; Gg[4 * qq + 2] = vg.z; Gg[4 * qq + 3] = vg.w;
            }
#pragma unroll
            for (int m = 0; m < 8; m++) {
                int jj = q4 * 8 + m;
                float gi = Gi[m] + xv * wih_s[jj]      + bias_s[jj];
                float gg = Gg[m] + xv * wih_s[64 + jj] + bias_s[64 + jj];
                ig[m] = sigm(gi) * tanh_(gg);
            }
            float Gf[8], Go[8];
#pragma unroll
            for (int qq = 0; qq < 2; qq++) {
                float4 vf = *(const float4*)&gsm[cb0 + 32 + 4 * qq];
                float4 vo = *(const float4*)&gsm[cb0 + 96 + 4 * qq];
                Gf[4 * qq] = vf.x; Gf[4 * qq + 1] = vf.y; Gf[4 * qq + 2] = vf.z; Gf[4 * qq + 3] = vf.w;
                Go[4 * qq] = vo.x; Go[4 * qq + 1] = vo.y; Go[4 * qq + 2] = vo.z; Go[4 * qq + 3] = vo.w;
            }
            float accy = 0.0f;
            uint32_t hw[4];
#pragma unroll
            for (int p = 0; p < 4; p++) {
                float h2[2];
#pragma unroll
                for (int e = 0; e < 2; e++) {
                    int m = 2 * p + e;
                    int jj = q4 * 8 + m;
                    float gf = Gf[m] + xv * wih_s[32 + jj] + bias_s[32 + jj];
                    float go = Go[m] + xv * wih_s[96 + jj] + bias_s[96 + jj];
                    float cn = sigm(gf) * c[m] + ig[m];
                    c[m] = cn;
                    float hv = sigm(go) * tanh_(cn);
                    h2[e] = hv;
                    accy += hv * wout_s[jj];
                }
                hw[p] = ((uint32_t)__half_as_ushort(__float2half(h2[1])) << 16)
                      |  (uint32_t)__half_as_ushort(__float2half(h2[0]));
            }
            uint4* dsth = (uint4*)((char*)g_h + ((size_t)(row0 + row) * Hh + j0 + q4 * 8) * 2);
            dsth[0] = make_uint4(hw[0], hw[1], hw[2], hw[3]);
            // reduce head partial over the 4 threads of this row (adjacent lanes)
            float accT = accy + __shfl_xor_sync(0xffffffffu, accy, 1);
            accT += __shfl_xor_sync(0xffffffffu, accT, 2);
            if (q4 == 0)
                atomicAdd(&out[(size_t)(row0 + row) * Tt + t], accT);
        }

        // ---- publish h(t+1 version): all writers fence, then one release-store ----
        __threadfence();
        __syncthreads();
        if (tid == 0) st_flag_release(myflag, t + 1);
    }
}

extern "C" void kernel_launch(void* const* d_in, const int* in_sizes, int n_in,
                              void* d_out, int out_size) {
    const float* x     = (const float*)d_in[0];
    const float* W_ih  = (const float*)d_in[1];
    const float* W_hh  = (const float*)d_in[2];
    const float* b_ih  = (const float*)d_in[3];
    const float* b_hh  = (const float*)d_in[4];
    const float* W_out = (const float*)d_in[5];
    const float* b_out = (const float*)d_in[6];
    float* out = (float*)d_out;

    cudaFuncSetAttribute(lstm_main, cudaFuncAttributeMaxDynamicSharedMemorySize, SMEM_DYN);

    prepack_kernel<<<2048, 256>>>(x, W_hh, b_out, out);
    lstm_main<<<NCTA, NTHREADS, SMEM_DYN>>>(W_ih, b_ih, b_hh, W_out, out);
}

// round 6
// speedup vs baseline: 1.5026x; 1.5026x over previous
#include <cuda_runtime.h>
#include <cuda_fp16.h>
#include <cstdint>

#define Bb 512
#define Tt 256
#define Hh 1024
#define NCTA 128
#define KCH 128
#define NCHUNK 8           // 1024 / 128
#define NSTG 3
#define STAGE_BYTES 65536  // A tile 32KB + B tile 32KB
#define NTHREADS 512
#define GP 132             // gates smem pitch (floats)
#define SMEM_DYN (1024 + 2048 + NSTG*STAGE_BYTES)

// persistent device state (static allocation — no cudaMalloc)
__device__ __half g_h[Bb * Hh];            // hidden state, fp16 [512,1024]
__device__ __half g_wp[32 * 128 * Hh];     // packed W_hh slabs, fp16
__device__ float  g_xT[Tt * Bb];           // x transposed [T,B]
__device__ int    g_bar;

// ---------------- helpers ----------------
__device__ __forceinline__ uint32_t smem_u32(const void* p) {
    uint32_t a;
    asm("{ .reg .u64 t; cvta.to.shared.u64 t, %1; cvt.u32.u64 %0, t; }" : "=r"(a) : "l"(p));
    return a;
}
__device__ __forceinline__ void cp16(uint32_t dst, const void* src) {
    unsigned long long g = __cvta_generic_to_global(src);
    asm volatile("cp.async.cg.shared.global [%0], [%1], 16;" :: "r"(dst), "l"(g) : "memory");
}
__device__ __forceinline__ void cp_commit() {
    asm volatile("cp.async.commit_group;" ::: "memory");
}
__device__ __forceinline__ void cp_wait1() {
    asm volatile("cp.async.wait_group 1;" ::: "memory");
}
__device__ __forceinline__ void cp_wait0() {
    asm volatile("cp.async.wait_group 0;" ::: "memory");
}
__device__ __forceinline__ void ldsm_x4(uint32_t (&r)[4], uint32_t addr) {
    asm volatile("ldmatrix.sync.aligned.m8n8.x4.shared.b16 {%0,%1,%2,%3}, [%4];"
        : "=r"(r[0]), "=r"(r[1]), "=r"(r[2]), "=r"(r[3]) : "r"(addr));
}
__device__ __forceinline__ void mma16816(float (&d)[4], const uint32_t (&a)[4],
                                         uint32_t b0, uint32_t b1) {
    asm volatile("mma.sync.aligned.m16n8k16.row.col.f32.f16.f16.f32 "
        "{%0,%1,%2,%3}, {%4,%5,%6,%7}, {%8,%9}, {%0,%1,%2,%3};"
        : "+f"(d[0]), "+f"(d[1]), "+f"(d[2]), "+f"(d[3])
        : "r"(a[0]), "r"(a[1]), "r"(a[2]), "r"(a[3]), "r"(b0), "r"(b1));
}
__device__ __forceinline__ float sigm(float x) { return 1.0f / (1.0f + __expf(-x)); }
__device__ __forceinline__ float tanh_(float x) { return 2.0f / (1.0f + __expf(-2.0f * x)) - 1.0f; }

// swizzled byte offset within a 128-row x 256B tile (granule = 16B)
__device__ __forceinline__ uint32_t swz(int r, int g) {
    return (uint32_t)(r * 256) + (uint32_t)(((g & 8) | ((g & 7) ^ (r & 7))) << 4);
}

// ---------------- prepack: weights->fp16 slabs, x transpose, h=0, out=b_out ----------------
__global__ void prepack_kernel(const float* __restrict__ x,
                               const float* __restrict__ W_hh,
                               const float* __restrict__ b_out,
                               float* __restrict__ out)
{
    long i = (long)blockIdx.x * blockDim.x + threadIdx.x;
    long stride = (long)gridDim.x * blockDim.x;
    // packed weights: slab jb, row r = gate*32 + jj  ->  W_hh[gate*H + jb*32 + jj, k]
    for (long idx = i; idx < (long)32 * 128 * Hh; idx += stride) {
        int k  = (int)(idx & (Hh - 1));
        int r  = (int)((idx >> 10) & 127);
        int jb = (int)(idx >> 17);
        int g  = r >> 5, jj = r & 31;
        g_wp[idx] = __float2half(W_hh[(long)(g * Hh + jb * 32 + jj) * Hh + k]);
    }
    for (long idx = i; idx < (long)Tt * Bb; idx += stride) {
        int b = (int)(idx & (Bb - 1));
        int t = (int)(idx >> 9);
        g_xT[idx] = x[(long)b * Tt + t];
    }
    for (long idx = i; idx < (long)Bb * Hh; idx += stride)
        g_h[idx] = __float2half(0.0f);
    float bo = b_out[0];
    for (long idx = i; idx < (long)Bb * Tt; idx += stride)
        out[idx] = bo;
    if (i == 0) g_bar = 0;
}

// ---------------- persistent LSTM kernel ----------------
__global__ void __launch_bounds__(NTHREADS, 1) lstm_main(
    const float* __restrict__ W_ih, const float* __restrict__ b_ih,
    const float* __restrict__ b_hh, const float* __restrict__ W_out,
    float* __restrict__ out)
{
    extern __shared__ char smem_raw[];
    uint32_t sraw = smem_u32(smem_raw);
    uint32_t s0 = (sraw + 1023u) & ~1023u;
    char* sm0 = smem_raw + (s0 - sraw);

    const int tid = threadIdx.x;
    const int l   = tid & 31;
    const int w   = tid >> 5;
    const int cta = blockIdx.x;
    const int mb = cta >> 5, jb = cta & 31;
    const int row0 = mb * 128, j0 = jb * 32;

    float* bias_s = (float*)(sm0);           // [128]
    float* wih_s  = (float*)(sm0 + 512);     // [128]
    float* wout_s = (float*)(sm0 + 1024);    // [32]
    const uint32_t TILE0 = s0 + 2048;        // pipeline stages / gates scratch (aliased)
    float* gsm = (float*)(sm0 + 2048);       // gates [128][GP] fp32, aliases stage 0

    if (tid < 128) {
        int g = tid >> 5, jj = tid & 31;
        int grow = g * Hh + j0 + jj;
        bias_s[tid] = b_ih[grow] + b_hh[grow];
        wih_s[tid]  = W_ih[grow];
    }
    if (tid < 32) wout_s[tid] = W_out[j0 + tid];
    __syncthreads();

    // warp tiling: 16 warps, M0 in {0,32,64,96} (w&3), N0 in {0,32,64,96} (w>>2)
    const int M0 = (w & 3) * 32;
    const int N0 = (w >> 2) * 32;
    // ldmatrix lane address components
    const int arow0 = M0 + (l & 7) + 8 * ((l >> 3) & 1);   // +16*mi
    const int agrn0 = (l >> 4);                             // + 2*kk
    const int brow0 = N0 + (l & 7) + 8 * (l >> 4);          // +16*p
    const int bgrn0 = (l >> 3) & 1;                         // + 2*kk
    const int l4 = l >> 2, l2 = (l & 3) * 2;

    const char* baseA = (const char*)g_h  + (size_t)row0 * (Hh * 2);
    const char* baseB = (const char*)g_wp + (size_t)jb * 128 * (Hh * 2);

    // cp granule mapping for one 32KB half-tile: 2048 granules of 16B, 4 per thread
    // q = tid + 512*j -> row q>>4, granule q&15
    float c[8];
#pragma unroll
    for (int m = 0; m < 8; m++) c[m] = 0.0f;

    const int row = tid >> 2, q4 = tid & 3;   // epilogue mapping: 4 threads per batch row

#pragma unroll 1
    for (int t = 0; t < Tt; t++) {
        // On entry: this thread's h(t-1) stores + threadfence already done (loop bottom).
        __syncthreads();
        // ---- arrive ASAP; then prefetch B (weights, h-independent) while spinning ----
        if (tid == 0) atomicAdd(&g_bar, 1);
#pragma unroll
        for (int s = 0; s < 2; s++) {        // B chunks 0,1 -> stages 0,1
            uint32_t tb = TILE0 + s * STAGE_BYTES + 32768;
#pragma unroll
            for (int j = 0; j < 4; j++) {
                int q = tid + 512 * j;
                int r = q >> 4, cb = q & 15;
                size_t go = (size_t)r * (Hh * 2) + (size_t)s * (KCH * 2) + (size_t)cb * 16;
                cp16(tb + swz(r, cb), baseB + go);
            }
            cp_commit();
        }
        // ---- spin for h(t-1) chip-wide ----
        if (tid == 0) {
            int target = NCTA * (t + 1);
            while (*(volatile int*)&g_bar < target) { }
        }
        __syncthreads();
        // ---- A (h) chunks 0,1 -> stages 0,1 ----
#pragma unroll
        for (int s = 0; s < 2; s++) {
            uint32_t tb = TILE0 + s * STAGE_BYTES;
#pragma unroll
            for (int j = 0; j < 4; j++) {
                int q = tid + 512 * j;
                int r = q >> 4, cb = q & 15;
                size_t go = (size_t)r * (Hh * 2) + (size_t)s * (KCH * 2) + (size_t)cb * 16;
                cp16(tb + swz(r, cb), baseA + go);
            }
            cp_commit();
        }

        float acc[2][4][4];
#pragma unroll
        for (int mi = 0; mi < 2; mi++)
#pragma unroll
            for (int ni = 0; ni < 4; ni++)
#pragma unroll
                for (int e = 0; e < 4; e++) acc[mi][ni][e] = 0.0f;

        // ---- main K loop: 8 chunks of 128 ----
#pragma unroll 1
        for (int ch = 0; ch < NCHUNK; ch++) {
            cp_wait1();
            __syncthreads();

            // issue chunk ch+2 into stage (ch+2)%3 (read finished at iter ch-1, sync'd)
            int nc = ch + 2;
            if (nc < NCHUNK) {
                uint32_t tb = TILE0 + (nc % NSTG) * STAGE_BYTES;
#pragma unroll
                for (int j = 0; j < 4; j++) {
                    int q = tid + 512 * j;
                    int r = q >> 4, cb = q & 15;
                    size_t go = (size_t)r * (Hh * 2) + (size_t)nc * (KCH * 2) + (size_t)cb * 16;
                    cp16(tb + swz(r, cb),         baseA + go);
                    cp16(tb + 32768 + swz(r, cb), baseB + go);
                }
            }
            cp_commit();

            uint32_t As = TILE0 + (ch % NSTG) * STAGE_BYTES;
            uint32_t Bs = As + 32768;

            uint32_t a[2][2][4];   // [buf][mi][4]
            uint32_t bf[2][4][2];  // [buf][ni][2]
            // prefetch kk=0
#pragma unroll
            for (int mi = 0; mi < 2; mi++) {
                int r2 = arow0 + 16 * mi;
                ldsm_x4(a[0][mi], As + swz(r2, agrn0));
            }
#pragma unroll
            for (int p = 0; p < 2; p++) {
                uint32_t b4[4];
                int r2 = brow0 + 16 * p;
                ldsm_x4(b4, Bs + swz(r2, bgrn0));
                bf[0][2 * p][0] = b4[0]; bf[0][2 * p][1] = b4[1];
                bf[0][2 * p + 1][0] = b4[2]; bf[0][2 * p + 1][1] = b4[3];
            }
#pragma unroll
            for (int kk = 0; kk < 8; kk++) {
                int cur = kk & 1, nxt = cur ^ 1;
                if (kk < 7) {
                    int gr_a = 2 * (kk + 1) + agrn0;
                    int gr_b = 2 * (kk + 1) + bgrn0;
#pragma unroll
                    for (int mi = 0; mi < 2; mi++) {
                        int r2 = arow0 + 16 * mi;
                        ldsm_x4(a[nxt][mi], As + swz(r2, gr_a));
                    }
#pragma unroll
                    for (int p = 0; p < 2; p++) {
                        uint32_t b4[4];
                        int r2 = brow0 + 16 * p;
                        ldsm_x4(b4, Bs + swz(r2, gr_b));
                        bf[nxt][2 * p][0] = b4[0]; bf[nxt][2 * p][1] = b4[1];
                        bf[nxt][2 * p + 1][0] = b4[2]; bf[nxt][2 * p + 1][1] = b4[3];
                    }
                }
#pragma unroll
                for (int mi = 0; mi < 2; mi++)
#pragma unroll
                    for (int ni = 0; ni < 4; ni++)
                        mma16816(acc[mi][ni], a[cur][mi], bf[cur][ni][0], bf[cur][ni][1]);
            }
        }
        cp_wait0();
        __syncthreads();   // all warps done reading stages before gates alias write

        // ---- store gates to smem (pitch GP=132, float2) ----
#pragma unroll
        for (int mi = 0; mi < 2; mi++)
#pragma unroll
            for (int ni = 0; ni < 4; ni++) {
                int r2 = M0 + mi * 16 + l4;
                int col = N0 + ni * 8 + l2;
                *(float2*)&gsm[r2 * GP + col]       = make_float2(acc[mi][ni][0], acc[mi][ni][1]);
                *(float2*)&gsm[(r2 + 8) * GP + col] = make_float2(acc[mi][ni][2], acc[mi][ni][3]);
            }
        __syncthreads();

        // ---- combine: 512 threads, thread = 4*row + q4, 8 jj each ----
        {
            float xv = g_xT[t * Bb + row0 + row];
            int cb0 = row * GP + q4 * 8;
            float Gi[8], Gg[8], ig[8];
#pragma unroll
            for (int qq = 0; qq < 2; qq++) {
                float4 vi = *(const float4*)&gsm[cb0 + 0  + 4 * qq];
                float4 vg = *(const float4*)&gsm[cb0 + 64 + 4 * qq];
                Gi[4 * qq] = vi.x; Gi[4 * qq + 1] = vi.y; Gi[4 * qq + 2] = vi.z; Gi[4 * qq + 3] = vi.w;
                Gg[4 * qq] = vg.x; Gg[4 * qq + 1] = vg.y; Gg[4 * qq + 2] = vg.z; Gg[4 * qq + 3] = vg.w;
            }
#pragma unroll
            for (int m = 0; m < 8; m++) {
                int jj = q4 * 8 + m;
                float gi = Gi[m] + xv * wih_s[jj]      + bias_s[jj];
                float gg = Gg[m] + xv * wih_s[64 + jj] + bias_s[64 + jj];
                ig[m] = sigm(gi) * tanh_(gg);
            }
            float Gf[8], Go[8];
#pragma unroll
            for (int qq = 0; qq < 2; qq++) {
                float4 vf = *(const float4*)&gsm[cb0 + 32 + 4 * qq];
                float4 vo = *(const float4*)&gsm[cb0 + 96 + 4 * qq];
                Gf[4 * qq] = vf.x; Gf[4 * qq + 1] = vf.y; Gf[4 * qq + 2] = vf.z; Gf[4 * qq + 3] = vf.w;
                Go[4 * qq] = vo.x; Go[4 * qq + 1] = vo.y; Go[4 * qq + 2] = vo.z; Go[4 * qq + 3] = vo.w;
            }
            float accy = 0.0f;
            uint32_t hw[4];
#pragma unroll
            for (int p = 0; p < 4; p++) {
                float h2[2];
#pragma unroll
                for (int e = 0; e < 2; e++) {
                    int m = 2 * p + e;
                    int jj = q4 * 8 + m;
                    float gf = Gf[m] + xv * wih_s[32 + jj] + bias_s[32 + jj];
                    float go = Go[m] + xv * wih_s[96 + jj] + bias_s[96 + jj];
                    float cn = sigm(gf) * c[m] + ig[m];
                    c[m] = cn;
                    float hv = sigm(go) * tanh_(cn);
                    h2[e] = hv;
                    accy += hv * wout_s[jj];
                }
                hw[p] = ((uint32_t)__half_as_ushort(__float2half(h2[1])) << 16)
                      |  (uint32_t)__half_as_ushort(__float2half(h2[0]));
            }
            uint4* dsth = (uint4*)((char*)g_h + ((size_t)(row0 + row) * Hh + j0 + q4 * 8) * 2);
            dsth[0] = make_uint4(hw[0], hw[1], hw[2], hw[3]);
            // h published before barrier; out-atomic issued AFTER fence (off critical path)
            __threadfence();
            float accT = accy + __shfl_xor_sync(0xffffffffu, accy, 1);
            accT += __shfl_xor_sync(0xffffffffu, accT, 2);
            if (q4 == 0)
                atomicAdd(&out[(size_t)(row0 + row) * Tt + t], accT);
        }
    }
}

extern "C" void kernel_launch(void* const* d_in, const int* in_sizes, int n_in,
                              void* d_out, int out_size) {
    const float* x     = (const float*)d_in[0];
    const float* W_ih  = (const float*)d_in[1];
    const float* W_hh  = (const float*)d_in[2];
    const float* b_ih  = (const float*)d_in[3];
    const float* b_hh  = (const float*)d_in[4];
    const float* W_out = (const float*)d_in[5];
    const float* b_out = (const float*)d_in[6];
    float* out = (float*)d_out;

    cudaFuncSetAttribute(lstm_main, cudaFuncAttributeMaxDynamicSharedMemorySize, SMEM_DYN);

    prepack_kernel<<<2048, 256>>>(x, W_hh, b_out, out);
    lstm_main<<<NCTA, NTHREADS, SMEM_DYN>>>(W_ih, b_ih, b_hh, W_out, out);
}

// round 7
// speedup vs baseline: 1.5704x; 1.0451x over previous
#include <cuda_runtime.h>
#include <cuda_fp16.h>
#include <cstdint>

#define Bb 512
#define Tt 256
#define Hh 1024
#define NCTA 128
#define KCH 128
#define NCHUNK 8           // 1024 / 128
#define NSTG 3
#define STAGE_BYTES 65536  // A tile 32KB + B tile 32KB
#define NTHREADS 512
#define SMEM_DYN (1024 + 2048 + NSTG*STAGE_BYTES)

// persistent device state (static allocation — no cudaMalloc)
__device__ __half g_h[Bb * Hh];            // hidden state, fp16 [512,1024]
__device__ __half g_wp[32 * 128 * Hh];     // packed W_hh slabs, fp16 (gate-interleaved)
__device__ float  g_xT[Tt * Bb];           // x transposed [T,B]
__device__ int    g_bar4[4];               // per-mb-group barrier counters

// ---------------- helpers ----------------
__device__ __forceinline__ uint32_t smem_u32(const void* p) {
    uint32_t a;
    asm("{ .reg .u64 t; cvta.to.shared.u64 t, %1; cvt.u32.u64 %0, t; }" : "=r"(a) : "l"(p));
    return a;
}
__device__ __forceinline__ void cp16(uint32_t dst, const void* src) {
    unsigned long long g = __cvta_generic_to_global(src);
    asm volatile("cp.async.cg.shared.global [%0], [%1], 16;" :: "r"(dst), "l"(g) : "memory");
}
__device__ __forceinline__ void cp_commit() {
    asm volatile("cp.async.commit_group;" ::: "memory");
}
__device__ __forceinline__ void cp_wait1() {
    asm volatile("cp.async.wait_group 1;" ::: "memory");
}
__device__ __forceinline__ void cp_wait0() {
    asm volatile("cp.async.wait_group 0;" ::: "memory");
}
__device__ __forceinline__ void ldsm_x4(uint32_t (&r)[4], uint32_t addr) {
    asm volatile("ldmatrix.sync.aligned.m8n8.x4.shared.b16 {%0,%1,%2,%3}, [%4];"
        : "=r"(r[0]), "=r"(r[1]), "=r"(r[2]), "=r"(r[3]) : "r"(addr));
}
__device__ __forceinline__ void mma16816(float (&d)[4], const uint32_t (&a)[4],
                                         uint32_t b0, uint32_t b1) {
    asm volatile("mma.sync.aligned.m16n8k16.row.col.f32.f16.f16.f32 "
        "{%0,%1,%2,%3}, {%4,%5,%6,%7}, {%8,%9}, {%0,%1,%2,%3};"
        : "+f"(d[0]), "+f"(d[1]), "+f"(d[2]), "+f"(d[3])
        : "r"(a[0]), "r"(a[1]), "r"(a[2]), "r"(a[3]), "r"(b0), "r"(b1));
}
__device__ __forceinline__ float sigm(float x) { return 1.0f / (1.0f + __expf(-x)); }
__device__ __forceinline__ float tanh_(float x) { return 2.0f / (1.0f + __expf(-2.0f * x)) - 1.0f; }

__device__ __forceinline__ void bar_arrive_release(int* p) {
    asm volatile("red.release.gpu.global.add.u32 [%0], %1;" :: "l"(p), "r"(1) : "memory");
}
__device__ __forceinline__ int ld_acquire(const int* p) {
    int v;
    asm volatile("ld.acquire.gpu.global.u32 %0, [%1];" : "=r"(v) : "l"(p) : "memory");
    return v;
}

// swizzled byte offset within a 128-row x 256B tile (granule = 16B)
__device__ __forceinline__ uint32_t swz(int r, int g) {
    return (uint32_t)(r * 256) + (uint32_t)(((g & 8) | ((g & 7) ^ (r & 7))) << 4);
}

// ---------------- prepack ----------------
// packed slab row r (0..127): ng=r>>5, gate=(r>>3)&3, jl=r&7
//   -> W_hh[gate*H + jb*32 + ng*8 + jl , k]
// so warp ng's 32 N-columns hold all 4 gates for jj = ng*8..ng*8+7
__global__ void prepack_kernel(const float* __restrict__ x,
                               const float* __restrict__ W_hh,
                               const float* __restrict__ b_out,
                               float* __restrict__ out)
{
    long i = (long)blockIdx.x * blockDim.x + threadIdx.x;
    long stride = (long)gridDim.x * blockDim.x;
    for (long idx = i; idx < (long)32 * 128 * Hh; idx += stride) {
        int k  = (int)(idx & (Hh - 1));
        int r  = (int)((idx >> 10) & 127);
        int jb = (int)(idx >> 17);
        int ng = r >> 5, g = (r >> 3) & 3, jl = r & 7;
        g_wp[idx] = __float2half(W_hh[(long)(g * Hh + jb * 32 + ng * 8 + jl) * Hh + k]);
    }
    for (long idx = i; idx < (long)Tt * Bb; idx += stride) {
        int b = (int)(idx & (Bb - 1));
        int t = (int)(idx >> 9);
        g_xT[idx] = x[(long)b * Tt + t];
    }
    for (long idx = i; idx < (long)Bb * Hh; idx += stride)
        g_h[idx] = __float2half(0.0f);
    float bo = b_out[0];
    for (long idx = i; idx < (long)Bb * Tt; idx += stride)
        out[idx] = bo;
    if (i < 4) g_bar4[i] = 0;
}

// ---------------- persistent LSTM kernel ----------------
__global__ void __launch_bounds__(NTHREADS, 1) lstm_main(
    const float* __restrict__ W_ih, const float* __restrict__ b_ih,
    const float* __restrict__ b_hh, const float* __restrict__ W_out,
    float* __restrict__ out)
{
    extern __shared__ char smem_raw[];
    uint32_t sraw = smem_u32(smem_raw);
    uint32_t s0 = (sraw + 1023u) & ~1023u;
    char* sm0 = smem_raw + (s0 - sraw);

    const int tid = threadIdx.x;
    const int l   = tid & 31;
    const int w   = tid >> 5;
    const int cta = blockIdx.x;
    const int mb = cta >> 5, jb = cta & 31;
    const int row0 = mb * 128, j0 = jb * 32;
    int* mybar = g_bar4 + mb;

    float* bias_s = (float*)(sm0);           // [128] gate*32 + jj
    float* wih_s  = (float*)(sm0 + 512);     // [128]
    float* wout_s = (float*)(sm0 + 1024);    // [32]
    float* xs     = (float*)(sm0 + 1152);    // [128] x column this step
    const uint32_t TILE0 = s0 + 2048;        // pipeline stages

    if (tid < 128) {
        int g = tid >> 5, jj = tid & 31;
        int grow = g * Hh + j0 + jj;
        bias_s[tid] = b_ih[grow] + b_hh[grow];
        wih_s[tid]  = W_ih[grow];
    }
    if (tid < 32) wout_s[tid] = W_out[j0 + tid];
    __syncthreads();

    // warp tiling: 16 warps, M0 in {0,32,64,96} (w&3), N0 = ng*32 (ng = w>>2)
    const int M0 = (w & 3) * 32;
    const int ng = w >> 2;
    const int N0 = ng * 32;
    // ldmatrix lane address components
    const int arow0 = M0 + (l & 7) + 8 * ((l >> 3) & 1);   // +16*mi
    const int agrn0 = (l >> 4);                             // + 2*kk
    const int brow0 = N0 + (l & 7) + 8 * (l >> 4);          // +16*p
    const int bgrn0 = (l >> 3) & 1;                         // + 2*kk
    const int l4 = l >> 2, l2 = (l & 3) * 2;
    const int jA = ng * 8 + l2;                             // jj for e=0 (global-in-slab)

    const char* baseA = (const char*)g_h  + (size_t)row0 * (Hh * 2);
    const char* baseB = (const char*)g_wp + (size_t)jb * 128 * (Hh * 2);

    float c[8];   // [mi*4 + rh*2 + e]
#pragma unroll
    for (int m = 0; m < 8; m++) c[m] = 0.0f;

#pragma unroll 1
    for (int t = 0; t < Tt; t++) {
        // h stores of prev step done by all threads; sync, then release-arrive
        __syncthreads();
        if (tid == 0) bar_arrive_release(mybar);
        if (tid < 128) xs[tid] = g_xT[t * Bb + row0 + tid];  // h-independent
        // ---- prefetch B (weights, h-independent) while barrier settles ----
#pragma unroll
        for (int s = 0; s < 2; s++) {        // B chunks 0,1 -> stages 0,1
            uint32_t tb = TILE0 + s * STAGE_BYTES + 32768;
#pragma unroll
            for (int j = 0; j < 4; j++) {
                int q = tid + 512 * j;
                int r = q >> 4, cb = q & 15;
                size_t go = (size_t)r * (Hh * 2) + (size_t)s * (KCH * 2) + (size_t)cb * 16;
                cp16(tb + swz(r, cb), baseB + go);
            }
            cp_commit();
        }
        // ---- spin for this mb-group's h(t-1) ----
        if (tid == 0) {
            int target = 32 * (t + 1);
            while (ld_acquire(mybar) < target) { }
        }
        __syncthreads();
        // ---- A (h) chunks 0,1 -> stages 0,1 ----
#pragma unroll
        for (int s = 0; s < 2; s++) {
            uint32_t tb = TILE0 + s * STAGE_BYTES;
#pragma unroll
            for (int j = 0; j < 4; j++) {
                int q = tid + 512 * j;
                int r = q >> 4, cb = q & 15;
                size_t go = (size_t)r * (Hh * 2) + (size_t)s * (KCH * 2) + (size_t)cb * 16;
                cp16(tb + swz(r, cb), baseA + go);
            }
            cp_commit();
        }

        float acc[2][4][4];
#pragma unroll
        for (int mi = 0; mi < 2; mi++)
#pragma unroll
            for (int ni = 0; ni < 4; ni++)
#pragma unroll
                for (int e = 0; e < 4; e++) acc[mi][ni][e] = 0.0f;

        // ---- main K loop: 8 chunks of 128 ----
#pragma unroll 1
        for (int ch = 0; ch < NCHUNK; ch++) {
            cp_wait1();
            __syncthreads();

            int nc = ch + 2;
            if (nc < NCHUNK) {
                uint32_t tb = TILE0 + (nc % NSTG) * STAGE_BYTES;
#pragma unroll
                for (int j = 0; j < 4; j++) {
                    int q = tid + 512 * j;
                    int r = q >> 4, cb = q & 15;
                    size_t go = (size_t)r * (Hh * 2) + (size_t)nc * (KCH * 2) + (size_t)cb * 16;
                    cp16(tb + swz(r, cb),         baseA + go);
                    cp16(tb + 32768 + swz(r, cb), baseB + go);
                }
            }
            cp_commit();

            uint32_t As = TILE0 + (ch % NSTG) * STAGE_BYTES;
            uint32_t Bs = As + 32768;

            uint32_t a[2][2][4];   // [buf][mi][4]
            uint32_t bf[2][4][2];  // [buf][ni][2]
#pragma unroll
            for (int mi = 0; mi < 2; mi++) {
                int r2 = arow0 + 16 * mi;
                ldsm_x4(a[0][mi], As + swz(r2, agrn0));
            }
#pragma unroll
            for (int p = 0; p < 2; p++) {
                uint32_t b4[4];
                int r2 = brow0 + 16 * p;
                ldsm_x4(b4, Bs + swz(r2, bgrn0));
                bf[0][2 * p][0] = b4[0]; bf[0][2 * p][1] = b4[1];
                bf[0][2 * p + 1][0] = b4[2]; bf[0][2 * p + 1][1] = b4[3];
            }
#pragma unroll
            for (int kk = 0; kk < 8; kk++) {
                int cur = kk & 1, nxt = cur ^ 1;
                if (kk < 7) {
                    int gr_a = 2 * (kk + 1) + agrn0;
                    int gr_b = 2 * (kk + 1) + bgrn0;
#pragma unroll
                    for (int mi = 0; mi < 2; mi++) {
                        int r2 = arow0 + 16 * mi;
                        ldsm_x4(a[nxt][mi], As + swz(r2, gr_a));
                    }
#pragma unroll
                    for (int p = 0; p < 2; p++) {
                        uint32_t b4[4];
                        int r2 = brow0 + 16 * p;
                        ldsm_x4(b4, Bs + swz(r2, gr_b));
                        bf[nxt][2 * p][0] = b4[0]; bf[nxt][2 * p][1] = b4[1];
                        bf[nxt][2 * p + 1][0] = b4[2]; bf[nxt][2 * p + 1][1] = b4[3];
                    }
                }
#pragma unroll
                for (int mi = 0; mi < 2; mi++)
#pragma unroll
                    for (int ni = 0; ni < 4; ni++)
                        mma16816(acc[mi][ni], a[cur][mi], bf[cur][ni][0], bf[cur][ni][1]);
            }
        }
        cp_wait0();
        __syncthreads();   // all stage reads/writes quiesced before next-step prefetch

        // ---- in-register combine: thread owns rows {M0+mi*16+l4+8*rh}, jj {jA, jA+1},
        //      and ALL FOUR GATES (ni = gate) for those coords ----
#pragma unroll
        for (int mi = 0; mi < 2; mi++) {
#pragma unroll
            for (int rh = 0; rh < 2; rh++) {
                int r = M0 + mi * 16 + rh * 8 + l4;
                float xv = xs[r];
                float hv2[2];
                float hsum = 0.0f;
#pragma unroll
                for (int e = 0; e < 2; e++) {
                    int idx = rh * 2 + e;
                    int jj = jA + e;
                    float gi = acc[mi][0][idx] + xv * wih_s[jj]      + bias_s[jj];
                    float gf = acc[mi][1][idx] + xv * wih_s[32 + jj] + bias_s[32 + jj];
                    float gg = acc[mi][2][idx] + xv * wih_s[64 + jj] + bias_s[64 + jj];
                    float go = acc[mi][3][idx] + xv * wih_s[96 + jj] + bias_s[96 + jj];
                    int cm = mi * 4 + rh * 2 + e;
                    float cn = sigm(gf) * c[cm] + sigm(gi) * tanh_(gg);
                    c[cm] = cn;
                    float hv = sigm(go) * tanh_(cn);
                    hv2[e] = hv;
                    hsum += hv * wout_s[jj];
                }
                *(__half2*)((char*)g_h + ((size_t)(row0 + r) * Hh + j0 + jA) * 2)
                    = __floats2half2_rn(hv2[0], hv2[1]);
                // reduce over the 4 lanes (l&3) sharing this row -> sum over warp's 8 jj
                hsum += __shfl_xor_sync(0xffffffffu, hsum, 1);
                hsum += __shfl_xor_sync(0xffffffffu, hsum, 2);
                if ((l & 3) == 0)
                    atomicAdd(&out[(size_t)(row0 + r) * Tt + t], hsum);
            }
        }
    }
}

extern "C" void kernel_launch(void* const* d_in, const int* in_sizes, int n_in,
                              void* d_out, int out_size) {
    const float* x     = (const float*)d_in[0];
    const float* W_ih  = (const float*)d_in[1];
    const float* W_hh  = (const float*)d_in[2];
    const float* b_ih  = (const float*)d_in[3];
    const float* b_hh  = (const float*)d_in[4];
    const float* W_out = (const float*)d_in[5];
    const float* b_out = (const float*)d_in[6];
    float* out = (float*)d_out;

    cudaFuncSetAttribute(lstm_main, cudaFuncAttributeMaxDynamicSharedMemorySize, SMEM_DYN);

    prepack_kernel<<<2048, 256>>>(x, W_hh, b_out, out);
    lstm_main<<<NCTA, NTHREADS, SMEM_DYN>>>(W_ih, b_ih, b_hh, W_out, out);
}

// round 8
// speedup vs baseline: 1.6802x; 1.0699x over previous
#include <cuda_runtime.h>
#include <cuda_fp16.h>
#include <cstdint>

#define Bb 512
#define Tt 256
#define Hh 1024
#define NCTA 128
#define KCH 64
#define NCHUNK 16          // 1024 / 64
#define NSTG 3
#define STAGE_BYTES 24576  // A tile 8KB + B tile 16KB
#define GRP_BYTES (NSTG * STAGE_BYTES)   // 73728 per group
#define NTHREADS 512
#define SMEM_DYN (2048 + 2 * GRP_BYTES + 1024)

// persistent device state (static allocation — no cudaMalloc)
__device__ __half g_h[Bb * Hh];            // hidden state, fp16 [512,1024]
__device__ __half g_wp[32 * 128 * Hh];     // packed W_hh slabs, fp16 (gate-interleaved)
__device__ float  g_xT[Tt * Bb];           // x transposed [T,B]
__device__ int    g_bar8[8];               // [mb][half] barrier counters

// ---------------- helpers ----------------
__device__ __forceinline__ uint32_t smem_u32(const void* p) {
    uint32_t a;
    asm("{ .reg .u64 t; cvta.to.shared.u64 t, %1; cvt.u32.u64 %0, t; }" : "=r"(a) : "l"(p));
    return a;
}
__device__ __forceinline__ void cp16(uint32_t dst, const void* src) {
    unsigned long long g = __cvta_generic_to_global(src);
    asm volatile("cp.async.cg.shared.global [%0], [%1], 16;" :: "r"(dst), "l"(g) : "memory");
}
__device__ __forceinline__ void cp_commit() {
    asm volatile("cp.async.commit_group;" ::: "memory");
}
__device__ __forceinline__ void cp_wait1() {
    asm volatile("cp.async.wait_group 1;" ::: "memory");
}
__device__ __forceinline__ void cp_wait0() {
    asm volatile("cp.async.wait_group 0;" ::: "memory");
}
__device__ __forceinline__ void bar_named(int id) {
    asm volatile("bar.sync %0, 256;" :: "r"(id) : "memory");
}
__device__ __forceinline__ void ldsm_x4(uint32_t (&r)[4], uint32_t addr) {
    asm volatile("ldmatrix.sync.aligned.m8n8.x4.shared.b16 {%0,%1,%2,%3}, [%4];"
        : "=r"(r[0]), "=r"(r[1]), "=r"(r[2]), "=r"(r[3]) : "r"(addr));
}
__device__ __forceinline__ void mma16816(float (&d)[4], const uint32_t (&a)[4],
                                         uint32_t b0, uint32_t b1) {
    asm volatile("mma.sync.aligned.m16n8k16.row.col.f32.f16.f16.f32 "
        "{%0,%1,%2,%3}, {%4,%5,%6,%7}, {%8,%9}, {%0,%1,%2,%3};"
        : "+f"(d[0]), "+f"(d[1]), "+f"(d[2]), "+f"(d[3])
        : "r"(a[0]), "r"(a[1]), "r"(a[2]), "r"(a[3]), "r"(b0), "r"(b1));
}
__device__ __forceinline__ float sigm(float x) { return 1.0f / (1.0f + __expf(-x)); }
__device__ __forceinline__ float tanh_(float x) { return 2.0f / (1.0f + __expf(-2.0f * x)) - 1.0f; }

__device__ __forceinline__ void bar_arrive_release(int* p) {
    asm volatile("red.release.gpu.global.add.u32 [%0], %1;" :: "l"(p), "r"(1) : "memory");
}
__device__ __forceinline__ int ld_acquire(const int* p) {
    int v;
    asm volatile("ld.acquire.gpu.global.u32 %0, [%1];" : "=r"(v) : "l"(p) : "memory");
    return v;
}

// swizzled byte offset within a 128B-row tile (granule = 16B, 8 per row)
__device__ __forceinline__ uint32_t swz(int r, int g) {
    return (uint32_t)(r * 128) + (uint32_t)(((g ^ (r & 7)) & 7) << 4);
}

// ---------------- prepack ----------------
// packed slab row r (0..127): ng=r>>5, gate=(r>>3)&3, jl=r&7
//   -> W_hh[gate*H + jb*32 + ng*8 + jl , k]  (warp ng holds all 4 gates for its 8 jj)
__global__ void prepack_kernel(const float* __restrict__ x,
                               const float* __restrict__ W_hh,
                               const float* __restrict__ b_out,
                               float* __restrict__ out)
{
    long i = (long)blockIdx.x * blockDim.x + threadIdx.x;
    long stride = (long)gridDim.x * blockDim.x;
    for (long idx = i; idx < (long)32 * 128 * Hh; idx += stride) {
        int k  = (int)(idx & (Hh - 1));
        int r  = (int)((idx >> 10) & 127);
        int jb = (int)(idx >> 17);
        int ng = r >> 5, g = (r >> 3) & 3, jl = r & 7;
        g_wp[idx] = __float2half(W_hh[(long)(g * Hh + jb * 32 + ng * 8 + jl) * Hh + k]);
    }
    for (long idx = i; idx < (long)Tt * Bb; idx += stride) {
        int b = (int)(idx & (Bb - 1));
        int t = (int)(idx >> 9);
        g_xT[idx] = x[(long)b * Tt + t];
    }
    for (long idx = i; idx < (long)Bb * Hh; idx += stride)
        g_h[idx] = __float2half(0.0f);
    float bo = b_out[0];
    for (long idx = i; idx < (long)Bb * Tt; idx += stride)
        out[idx] = bo;
    if (i < 8) g_bar8[i] = 0;
}

// ---------------- persistent LSTM kernel: 2 independent warp-groups ----------------
__global__ void __launch_bounds__(NTHREADS, 1) lstm_main(
    const float* __restrict__ W_ih, const float* __restrict__ b_ih,
    const float* __restrict__ b_hh, const float* __restrict__ W_out,
    float* __restrict__ out)
{
    extern __shared__ char smem_raw[];
    uint32_t sraw = smem_u32(smem_raw);
    uint32_t s0 = (sraw + 1023u) & ~1023u;
    char* sm0 = smem_raw + (s0 - sraw);

    const int tid  = threadIdx.x;
    const int l    = tid & 31;
    const int w    = tid >> 5;
    const int g    = w >> 3;          // warp-group (batch half)
    const int lw   = w & 7;           // warp within group
    const int ltid = tid & 255;
    const int cta = blockIdx.x;
    const int mb = cta >> 5, jb = cta & 31;
    const int row0 = mb * 128, j0 = jb * 32;
    int* mybar = g_bar8 + mb * 2 + g;
    const int barid = 1 + g;

    float* bias_s = (float*)(sm0);           // [128] gate*32 + jj
    float* wih_s  = (float*)(sm0 + 512);     // [128]
    float* wout_s = (float*)(sm0 + 1024);    // [32]
    float* xs     = (float*)(sm0 + 1152);    // [128] x rows of this block (both halves)
    const uint32_t GTILE = s0 + 2048 + (uint32_t)g * GRP_BYTES;  // this group's stages

    if (tid < 128) {
        int gg = tid >> 5, jj = tid & 31;
        int grow = gg * Hh + j0 + jj;
        bias_s[tid] = b_ih[grow] + b_hh[grow];
        wih_s[tid]  = W_ih[grow];
    }
    if (tid < 32) wout_s[tid] = W_out[j0 + tid];
    __syncthreads();

    // warp tiling within group: lw -> Mg = lw&1 (32-row tile), ng = lw>>1 (32 gate-cols)
    const int M0 = (lw & 1) * 32;
    const int ng = lw >> 1;
    const int N0 = ng * 32;
    const int arow0 = M0 + (l & 7) + 8 * ((l >> 3) & 1);   // +16*mi
    const int agrn0 = (l >> 4);                             // + 2*kk
    const int brow0 = N0 + (l & 7) + 8 * (l >> 4);          // +16*p
    const int bgrn0 = (l >> 3) & 1;                         // + 2*kk
    const int l4 = l >> 2, l2 = (l & 3) * 2;
    const int jA = ng * 8 + l2;

    const char* baseA = (const char*)g_h  + (size_t)(row0 + g * 64) * (Hh * 2);
    const char* baseB = (const char*)g_wp + (size_t)jb * 128 * (Hh * 2);

    float c[8];   // [mi*4 + rh*2 + e]
#pragma unroll
    for (int m = 0; m < 8; m++) c[m] = 0.0f;

#pragma unroll 1
    for (int t = 0; t < Tt; t++) {
        // ---- x rows for this half (h-independent); stages quiesced by end-of-step bar ----
        if (ltid < 64) xs[g * 64 + ltid] = g_xT[t * Bb + row0 + g * 64 + ltid];
        // ---- B prefetch chunks 0,1 (h-independent, issued before the spin) ----
#pragma unroll
        for (int s = 0; s < 2; s++) {
            uint32_t tb = GTILE + s * STAGE_BYTES + 8192;
#pragma unroll
            for (int j = 0; j < 4; j++) {
                int q = ltid + 256 * j;
                int r = q >> 3, cb = q & 7;
                size_t go = (size_t)r * (Hh * 2) + (size_t)s * (KCH * 2) + (size_t)cb * 16;
                cp16(tb + swz(r, cb), baseB + go);
            }
            cp_commit();
        }
        // ---- spin: this half's h(t-1) published by all 32 CTAs of the mb-group ----
        if (ltid == 0) {
            int target = 32 * t;
            while (ld_acquire(mybar) < target) { }
        }
        bar_named(barid);
        // ---- A prefetch chunks 0,1 ----
#pragma unroll
        for (int s = 0; s < 2; s++) {
            uint32_t tb = GTILE + s * STAGE_BYTES;
#pragma unroll
            for (int j = 0; j < 2; j++) {
                int q = ltid + 256 * j;
                int r = q >> 3, cb = q & 7;
                size_t go = (size_t)r * (Hh * 2) + (size_t)s * (KCH * 2) + (size_t)cb * 16;
                cp16(tb + swz(r, cb), baseA + go);
            }
            cp_commit();
        }

        float acc[2][4][4];
#pragma unroll
        for (int mi = 0; mi < 2; mi++)
#pragma unroll
            for (int ni = 0; ni < 4; ni++)
#pragma unroll
                for (int e = 0; e < 4; e++) acc[mi][ni][e] = 0.0f;

        // ---- main K loop: 16 chunks of 64 ----
#pragma unroll 1
        for (int ch = 0; ch < NCHUNK; ch++) {
            cp_wait1();
            bar_named(barid);   // all group warps done reading stage (ch+2)%3 (chunk ch-1)

            int nc = ch + 2;
            if (nc < NCHUNK) {
                uint32_t tb = GTILE + (nc % NSTG) * STAGE_BYTES;
#pragma unroll
                for (int j = 0; j < 2; j++) {
                    int q = ltid + 256 * j;
                    int r = q >> 3, cb = q & 7;
                    size_t go = (size_t)r * (Hh * 2) + (size_t)nc * (KCH * 2) + (size_t)cb * 16;
                    cp16(tb + swz(r, cb), baseA + go);
                }
#pragma unroll
                for (int j = 0; j < 4; j++) {
                    int q = ltid + 256 * j;
                    int r = q >> 3, cb = q & 7;
                    size_t go = (size_t)r * (Hh * 2) + (size_t)nc * (KCH * 2) + (size_t)cb * 16;
                    cp16(tb + 8192 + swz(r, cb), baseB + go);
                }
            }
            cp_commit();   // unconditional (empty group when nc >= NCHUNK)

            uint32_t As = GTILE + (ch % NSTG) * STAGE_BYTES;
            uint32_t Bs = As + 8192;

            uint32_t a[2][2][4];   // [buf][mi][4]
            uint32_t bf[2][4][2];  // [buf][ni][2]
#pragma unroll
            for (int mi = 0; mi < 2; mi++) {
                int r2 = arow0 + 16 * mi;
                ldsm_x4(a[0][mi], As + swz(r2, agrn0));
            }
#pragma unroll
            for (int p = 0; p < 2; p++) {
                uint32_t b4[4];
                int r2 = brow0 + 16 * p;
                ldsm_x4(b4, Bs + swz(r2, bgrn0));
                bf[0][2 * p][0] = b4[0]; bf[0][2 * p][1] = b4[1];
                bf[0][2 * p + 1][0] = b4[2]; bf[0][2 * p + 1][1] = b4[3];
            }
#pragma unroll
            for (int kk = 0; kk < 4; kk++) {
                int cur = kk & 1, nxt = cur ^ 1;
                if (kk < 3) {
                    int gr_a = 2 * (kk + 1) + agrn0;
                    int gr_b = 2 * (kk + 1) + bgrn0;
#pragma unroll
                    for (int mi = 0; mi < 2; mi++) {
                        int r2 = arow0 + 16 * mi;
                        ldsm_x4(a[nxt][mi], As + swz(r2, gr_a));
                    }
#pragma unroll
                    for (int p = 0; p < 2; p++) {
                        uint32_t b4[4];
                        int r2 = brow0 + 16 * p;
                        ldsm_x4(b4, Bs + swz(r2, gr_b));
                        bf[nxt][2 * p][0] = b4[0]; bf[nxt][2 * p][1] = b4[1];
                        bf[nxt][2 * p + 1][0] = b4[2]; bf[nxt][2 * p + 1][1] = b4[3];
                    }
                }
#pragma unroll
                for (int mi = 0; mi < 2; mi++)
#pragma unroll
                    for (int ni = 0; ni < 4; ni++)
                        mma16816(acc[mi][ni], a[cur][mi], bf[cur][ni][0], bf[cur][ni][1]);
            }
        }
        cp_wait0();
        bar_named(barid);   // stages quiesced before next-iteration prefetch

        // ---- in-register LSTM combine: thread owns rows {M0+mi*16+rh*8+l4},
        //      jj {jA,jA+1}, and all four gates (ni = gate) ----
#pragma unroll
        for (int mi = 0; mi < 2; mi++) {
#pragma unroll
            for (int rh = 0; rh < 2; rh++) {
                int rl = M0 + mi * 16 + rh * 8 + l4;
                float xv = xs[g * 64 + rl];
                float hv2[2];
                float hsum = 0.0f;
#pragma unroll
                for (int e = 0; e < 2; e++) {
                    int idx = rh * 2 + e;
                    int jj = jA + e;
                    float gi = acc[mi][0][idx] + xv * wih_s[jj]      + bias_s[jj];
                    float gf = acc[mi][1][idx] + xv * wih_s[32 + jj] + bias_s[32 + jj];
                    float gg = acc[mi][2][idx] + xv * wih_s[64 + jj] + bias_s[64 + jj];
                    float go = acc[mi][3][idx] + xv * wih_s[96 + jj] + bias_s[96 + jj];
                    int cm = mi * 4 + rh * 2 + e;
                    float cn = sigm(gf) * c[cm] + sigm(gi) * tanh_(gg);
                    c[cm] = cn;
                    float hv = sigm(go) * tanh_(cn);
                    hv2[e] = hv;
                    hsum += hv * wout_s[jj];
                }
                int growr = row0 + g * 64 + rl;
                *(__half2*)((char*)g_h + ((size_t)growr * Hh + j0 + jA) * 2)
                    = __floats2half2_rn(hv2[0], hv2[1]);
                hsum += __shfl_xor_sync(0xffffffffu, hsum, 1);
                hsum += __shfl_xor_sync(0xffffffffu, hsum, 2);
                if ((l & 3) == 0)
                    atomicAdd(&out[(size_t)growr * Tt + t], hsum);
            }
        }
        // ---- publish this half's h(t): group-sync then one release-arrive ----
        bar_named(barid);
        if (ltid == 0) bar_arrive_release(mybar);
    }
}

extern "C" void kernel_launch(void* const* d_in, const int* in_sizes, int n_in,
                              void* d_out, int out_size) {
    const float* x     = (const float*)d_in[0];
    const float* W_ih  = (const float*)d_in[1];
    const float* W_hh  = (const float*)d_in[2];
    const float* b_ih  = (const float*)d_in[3];
    const float* b_hh  = (const float*)d_in[4];
    const float* W_out = (const float*)d_in[5];
    const float* b_out = (const float*)d_in[6];
    float* out = (float*)d_out;

    cudaFuncSetAttribute(lstm_main, cudaFuncAttributeMaxDynamicSharedMemorySize, SMEM_DYN);

    prepack_kernel<<<2048, 256>>>(x, W_hh, b_out, out);
    lstm_main<<<NCTA, NTHREADS, SMEM_DYN>>>(W_ih, b_ih, b_hh, W_out, out);
}